// round 4
// baseline (speedup 1.0000x reference)
#include <cuda_runtime.h>
#include <cuda_bf16.h>
#include <math.h>

// ---------------- problem constants ----------------
#define BB      4
#define SS      2048
#define HIDDEN  1024
#define HEADS   16
#define DH      64
#define LAYERS  4
#define IN_DIM  512
#define OUT_DIM 1024
#define FF_DIM  4096
#define M_ROWS  (BB * SS)          // 8192

// ---------------- scratch (no allocation allowed) ----------------
__device__ float g_h  [(size_t)M_ROWS * HIDDEN];      // hidden state
__device__ float g_qkv[(size_t)M_ROWS * 3 * HIDDEN];  // qkv proj
__device__ float g_ctx[(size_t)M_ROWS * HIDDEN];      // attention context / final-LN out
__device__ float g_y  [(size_t)M_ROWS * HIDDEN];      // gemm out before LN
__device__ float g_ff [(size_t)M_ROWS * FF_DIM];      // ff intermediate

// =================================================================
// Tiled SGEMM:  C[M,N] = A[M,K] @ W[K,N] + bias, row-major everywhere.
// EPI: 0 = bias only, 1 = bias+relu, 2 = bias then *sqrt(HIDDEN)+posenc
// BM=BN=128, BK=8, 256 threads, 8x8 per thread.
// =================================================================
template<int EPI>
__global__ void __launch_bounds__(256)
sgemm_kernel(const float* __restrict__ A, const float* __restrict__ W,
             const float* __restrict__ bias, float* __restrict__ C,
             int M, int N, int K)
{
    __shared__ __align__(16) float As[8][128];
    __shared__ __align__(16) float Bs[8][128];

    const int tid = threadIdx.x;
    const int tx = tid & 15;          // 0..15 -> col group
    const int ty = tid >> 4;          // 0..15 -> row group
    const int cb = blockIdx.x * 128;
    const int rb = blockIdx.y * 128;

    const int arow = tid >> 1;        // 0..127
    const int acol = (tid & 1) * 4;   // 0 or 4
    const int brow = tid >> 5;        // 0..7
    const int bcol = (tid & 31) * 4;  // 0..124

    const float* Ap = A + (size_t)(rb + arow) * K + acol;
    const float* Wp = W + (size_t)brow * N + cb + bcol;

    float acc[8][8];
#pragma unroll
    for (int i = 0; i < 8; i++)
#pragma unroll
        for (int j = 0; j < 8; j++) acc[i][j] = 0.f;

    for (int k0 = 0; k0 < K; k0 += 8) {
        float4 a4 = *(const float4*)(Ap + k0);
        float4 b4 = *(const float4*)(Wp + (size_t)k0 * N);
        As[acol + 0][arow] = a4.x;
        As[acol + 1][arow] = a4.y;
        As[acol + 2][arow] = a4.z;
        As[acol + 3][arow] = a4.w;
        *(float4*)&Bs[brow][bcol] = b4;
        __syncthreads();

#pragma unroll
        for (int kk = 0; kk < 8; kk++) {
            float4 a0 = *(const float4*)&As[kk][ty * 8];
            float4 a1 = *(const float4*)&As[kk][ty * 8 + 4];
            float4 b0 = *(const float4*)&Bs[kk][tx * 8];
            float4 b1 = *(const float4*)&Bs[kk][tx * 8 + 4];
            float av[8] = {a0.x, a0.y, a0.z, a0.w, a1.x, a1.y, a1.z, a1.w};
            float bv[8] = {b0.x, b0.y, b0.z, b0.w, b1.x, b1.y, b1.z, b1.w};
#pragma unroll
            for (int i = 0; i < 8; i++)
#pragma unroll
                for (int j = 0; j < 8; j++)
                    acc[i][j] += av[i] * bv[j];
        }
        __syncthreads();
    }

    // epilogue
    float4 bb0 = *(const float4*)&bias[cb + tx * 8];
    float4 bb1 = *(const float4*)&bias[cb + tx * 8 + 4];
    float bv[8] = {bb0.x, bb0.y, bb0.z, bb0.w, bb1.x, bb1.y, bb1.z, bb1.w};

#pragma unroll
    for (int i = 0; i < 8; i++) {
        int row = rb + ty * 8 + i;
        float* Cp = C + (size_t)row * N + cb + tx * 8;
        float o[8];
#pragma unroll
        for (int j = 0; j < 8; j++) {
            float c = acc[i][j] + bv[j];
            if (EPI == 1) c = fmaxf(c, 0.f);
            if (EPI == 2) {
                int col = cb + tx * 8 + j;
                int srow = row & (SS - 1);
                // div = exp(-(ln 10000)/1024 * (col & ~1)); even col -> sin, odd -> cos
                float freq = expf(-9.210340371976184f * (float)(col & ~1) * (1.0f / 1024.0f));
                float ang = (float)srow * freq;
                float pv = (col & 1) ? cosf(ang) : sinf(ang);
                c = c * 32.0f + pv;   // sqrt(1024) = 32
            }
            o[j] = c;
        }
        float4 o0 = {o[0], o[1], o[2], o[3]};
        float4 o1 = {o[4], o[5], o[6], o[7]};
        *(float4*)(Cp)     = o0;
        *(float4*)(Cp + 4) = o1;
    }
}

// =================================================================
// Flash attention: per block one (b, h, 64-row q tile).
// qkv layout [B, S, 3, HEADS, DH]; ctx output [B, S, HIDDEN].
// 256 threads as 16x16; each thread owns a 4x4 microtile.
// =================================================================
#define ATILE   64
#define ASTRIDE 65
#define ATTN_SMEM (4 * 64 * ASTRIDE * sizeof(float))   // Q,K,V,P = 66560 B

__global__ void __launch_bounds__(256)
attn_kernel(const float* __restrict__ qkv, float* __restrict__ ctx)
{
    extern __shared__ float sm[];
    float* Qs = sm;
    float* Ks = Qs + 64 * ASTRIDE;
    float* Vs = Ks + 64 * ASTRIDE;
    float* Ps = Vs + 64 * ASTRIDE;

    const int tid = threadIdx.x;
    const int tx = tid & 15;
    const int ty = tid >> 4;
    const int q0 = blockIdx.x * ATILE;
    const int h  = blockIdx.y;
    const int b  = blockIdx.z;

    // ---- load Q tile (64 rows x 64 dims) ----
    {
        int r = tid >> 2;
        const float* qp = qkv + (size_t)((b * SS + q0 + r) * 3) * HIDDEN + h * DH;
#pragma unroll
        for (int u = 0; u < 4; u++) {
            int d = ((tid & 3) + u * 4) * 4;
            float4 v = *(const float4*)(qp + d);
            Qs[r * ASTRIDE + d + 0] = v.x;
            Qs[r * ASTRIDE + d + 1] = v.y;
            Qs[r * ASTRIDE + d + 2] = v.z;
            Qs[r * ASTRIDE + d + 3] = v.w;
        }
    }

    float m_i[4], l_i[4], acc[4][4];
#pragma unroll
    for (int i = 0; i < 4; i++) {
        m_i[i] = -1e30f;
        l_i[i] = 0.f;
#pragma unroll
        for (int j = 0; j < 4; j++) acc[i][j] = 0.f;
    }

    for (int kt = 0; kt < SS / ATILE; kt++) {
        __syncthreads();   // protect smem from previous iteration's readers
        {
            int r = tid >> 2;
            size_t grow = (size_t)(b * SS + kt * ATILE + r) * 3;
            const float* kp = qkv + (grow + 1) * HIDDEN + h * DH;
            const float* vp = qkv + (grow + 2) * HIDDEN + h * DH;
#pragma unroll
            for (int u = 0; u < 4; u++) {
                int d = ((tid & 3) + u * 4) * 4;
                float4 kv = *(const float4*)(kp + d);
                float4 vv = *(const float4*)(vp + d);
                Ks[r * ASTRIDE + d + 0] = kv.x; Ks[r * ASTRIDE + d + 1] = kv.y;
                Ks[r * ASTRIDE + d + 2] = kv.z; Ks[r * ASTRIDE + d + 3] = kv.w;
                Vs[r * ASTRIDE + d + 0] = vv.x; Vs[r * ASTRIDE + d + 1] = vv.y;
                Vs[r * ASTRIDE + d + 2] = vv.z; Vs[r * ASTRIDE + d + 3] = vv.w;
            }
        }
        __syncthreads();

        // ---- scores: s = (Q @ K^T) / sqrt(dh) ----
        float s[4][4];
#pragma unroll
        for (int i = 0; i < 4; i++)
#pragma unroll
            for (int j = 0; j < 4; j++) s[i][j] = 0.f;

#pragma unroll 8
        for (int d = 0; d < DH; d++) {
            float q[4], k[4];
#pragma unroll
            for (int i = 0; i < 4; i++) q[i] = Qs[(ty * 4 + i) * ASTRIDE + d];
#pragma unroll
            for (int j = 0; j < 4; j++) k[j] = Ks[(tx * 4 + j) * ASTRIDE + d];
#pragma unroll
            for (int i = 0; i < 4; i++)
#pragma unroll
                for (int j = 0; j < 4; j++)
                    s[i][j] += q[i] * k[j];
        }

        // ---- online softmax update ----
#pragma unroll
        for (int i = 0; i < 4; i++) {
            float rm = -1e30f;
#pragma unroll
            for (int j = 0; j < 4; j++) {
                s[i][j] *= 0.125f;   // 1/sqrt(64)
                rm = fmaxf(rm, s[i][j]);
            }
#pragma unroll
            for (int off = 8; off > 0; off >>= 1)
                rm = fmaxf(rm, __shfl_xor_sync(0xffffffffu, rm, off));
            float mn = fmaxf(m_i[i], rm);
            float p[4], rs = 0.f;
#pragma unroll
            for (int j = 0; j < 4; j++) {
                p[j] = __expf(s[i][j] - mn);
                rs += p[j];
            }
#pragma unroll
            for (int off = 8; off > 0; off >>= 1)
                rs += __shfl_xor_sync(0xffffffffu, rs, off);
            float alpha = __expf(m_i[i] - mn);
            l_i[i] = l_i[i] * alpha + rs;
            m_i[i] = mn;
#pragma unroll
            for (int j = 0; j < 4; j++) {
                acc[i][j] *= alpha;
                Ps[(ty * 4 + i) * ASTRIDE + tx * 4 + j] = p[j];
            }
        }
        __syncthreads();

        // ---- acc += P @ V ----
#pragma unroll 8
        for (int k = 0; k < ATILE; k++) {
            float pr[4], vc[4];
#pragma unroll
            for (int i = 0; i < 4; i++) pr[i] = Ps[(ty * 4 + i) * ASTRIDE + k];
#pragma unroll
            for (int j = 0; j < 4; j++) vc[j] = Vs[k * ASTRIDE + tx * 4 + j];
#pragma unroll
            for (int i = 0; i < 4; i++)
#pragma unroll
                for (int j = 0; j < 4; j++)
                    acc[i][j] += pr[i] * vc[j];
        }
    }

    // ---- write ctx ----
#pragma unroll
    for (int i = 0; i < 4; i++) {
        float inv = 1.0f / l_i[i];
        int row = q0 + ty * 4 + i;
#pragma unroll
        for (int j = 0; j < 4; j++)
            ctx[(size_t)(b * SS + row) * HIDDEN + h * DH + tx * 4 + j] = acc[i][j] * inv;
    }
}

// =================================================================
// LayerNorm: one block per row of 1024.  out = LN(x + res) * g + b
// res may be nullptr (plain LN).
// =================================================================
__global__ void __launch_bounds__(256)
ln_kernel(const float* __restrict__ x, const float* __restrict__ res,
          const float* __restrict__ g, const float* __restrict__ beta,
          float* __restrict__ out)
{
    const int row = blockIdx.x;
    const int t = threadIdx.x;

    float4 v = ((const float4*)(x + (size_t)row * HIDDEN))[t];
    if (res) {
        float4 r = ((const float4*)(res + (size_t)row * HIDDEN))[t];
        v.x += r.x; v.y += r.y; v.z += r.z; v.w += r.w;
    }
    float s  = v.x + v.y + v.z + v.w;
    float sq = v.x * v.x + v.y * v.y + v.z * v.z + v.w * v.w;

#pragma unroll
    for (int off = 16; off > 0; off >>= 1) {
        s  += __shfl_xor_sync(0xffffffffu, s,  off);
        sq += __shfl_xor_sync(0xffffffffu, sq, off);
    }
    __shared__ float ss[8], ssq[8];
    __shared__ float smean, srstd;
    int warp = t >> 5, lane = t & 31;
    if (lane == 0) { ss[warp] = s; ssq[warp] = sq; }
    __syncthreads();
    if (t == 0) {
        float S = 0.f, Q = 0.f;
#pragma unroll
        for (int i = 0; i < 8; i++) { S += ss[i]; Q += ssq[i]; }
        float mean = S * (1.0f / HIDDEN);
        float var  = Q * (1.0f / HIDDEN) - mean * mean;
        smean = mean;
        srstd = rsqrtf(var + 1e-5f);
    }
    __syncthreads();
    float mean = smean, rstd = srstd;

    float4 gg = ((const float4*)g)[t];
    float4 bb = ((const float4*)beta)[t];
    float4 o;
    o.x = (v.x - mean) * rstd * gg.x + bb.x;
    o.y = (v.y - mean) * rstd * gg.y + bb.y;
    o.z = (v.z - mean) * rstd * gg.z + bb.z;
    o.w = (v.w - mean) * rstd * gg.w + bb.w;
    ((float4*)(out + (size_t)row * HIDDEN))[t] = o;
}

// =================================================================
// launch
// =================================================================
extern "C" void kernel_launch(void* const* d_in, const int* in_sizes, int n_in,
                              void* d_out, int out_size)
{
    const float* x     = (const float*)d_in[0];
    const float* in_W  = (const float*)d_in[1];
    const float* in_b  = (const float*)d_in[2];
    const float* qkv_W = (const float*)d_in[3];
    const float* qkv_b = (const float*)d_in[4];
    const float* out_W = (const float*)d_in[5];
    const float* out_b = (const float*)d_in[6];
    const float* ln1_g = (const float*)d_in[7];
    const float* ln1_b = (const float*)d_in[8];
    const float* ln2_g = (const float*)d_in[9];
    const float* ln2_b = (const float*)d_in[10];
    const float* ff1_W = (const float*)d_in[11];
    const float* ff1_b = (const float*)d_in[12];
    const float* ff2_W = (const float*)d_in[13];
    const float* ff2_b = (const float*)d_in[14];
    const float* fin_g = (const float*)d_in[15];
    const float* fin_b = (const float*)d_in[16];
    const float* op_W  = (const float*)d_in[17];
    const float* op_b  = (const float*)d_in[18];
    float* out = (float*)d_out;

    float *h, *qkv, *ctx, *y, *ff;
    cudaGetSymbolAddress((void**)&h,   g_h);
    cudaGetSymbolAddress((void**)&qkv, g_qkv);
    cudaGetSymbolAddress((void**)&ctx, g_ctx);
    cudaGetSymbolAddress((void**)&y,   g_y);
    cudaGetSymbolAddress((void**)&ff,  g_ff);

    cudaFuncSetAttribute(attn_kernel, cudaFuncAttributeMaxDynamicSharedMemorySize,
                         (int)ATTN_SMEM);

    const int M = M_ROWS;
    dim3 blk(256);

    // input projection + sqrt(H)*scale + positional encoding
    sgemm_kernel<2><<<dim3(HIDDEN / 128, M / 128), blk>>>(x, in_W, in_b, h, M, HIDDEN, IN_DIM);

    for (int l = 0; l < LAYERS; l++) {
        const float* qW = qkv_W + (size_t)l * HIDDEN * 3 * HIDDEN;
        const float* qb = qkv_b + (size_t)l * 3 * HIDDEN;
        const float* oW = out_W + (size_t)l * HIDDEN * HIDDEN;
        const float* ob = out_b + (size_t)l * HIDDEN;
        const float* f1W = ff1_W + (size_t)l * HIDDEN * FF_DIM;
        const float* f1b = ff1_b + (size_t)l * FF_DIM;
        const float* f2W = ff2_W + (size_t)l * FF_DIM * HIDDEN;
        const float* f2b = ff2_b + (size_t)l * HIDDEN;

        sgemm_kernel<0><<<dim3(3 * HIDDEN / 128, M / 128), blk>>>(h, qW, qb, qkv, M, 3 * HIDDEN, HIDDEN);
        attn_kernel<<<dim3(SS / ATILE, HEADS, BB), blk, ATTN_SMEM>>>(qkv, ctx);
        sgemm_kernel<0><<<dim3(HIDDEN / 128, M / 128), blk>>>(ctx, oW, ob, y, M, HIDDEN, HIDDEN);
        ln_kernel<<<M, blk>>>(h, y, ln1_g + l * HIDDEN, ln1_b + l * HIDDEN, h);
        sgemm_kernel<1><<<dim3(FF_DIM / 128, M / 128), blk>>>(h, f1W, f1b, ff, M, FF_DIM, HIDDEN);
        sgemm_kernel<0><<<dim3(HIDDEN / 128, M / 128), blk>>>(ff, f2W, f2b, y, M, HIDDEN, FF_DIM);
        ln_kernel<<<M, blk>>>(h, y, ln2_g + l * HIDDEN, ln2_b + l * HIDDEN, h);
    }

    // final LN then output projection
    ln_kernel<<<M, blk>>>(h, nullptr, fin_g, fin_b, ctx);
    sgemm_kernel<0><<<dim3(OUT_DIM / 128, M / 128), blk>>>(ctx, op_W, op_b, out, M, OUT_DIM, HIDDEN);
}

// round 6
// speedup vs baseline: 1.2555x; 1.2555x over previous
#include <cuda_runtime.h>
#include <cuda_bf16.h>
#include <math.h>
#include <stdint.h>

// ---------------- problem constants ----------------
#define BB      4
#define SS      2048
#define HIDDEN  1024
#define HEADS   16
#define DH      64
#define LAYERS  4
#define IN_DIM  512
#define OUT_DIM 1024
#define FF_DIM  4096
#define M_ROWS  (BB * SS)          // 8192

// ---------------- scratch (no allocation allowed) ----------------
__device__ float g_h  [(size_t)M_ROWS * HIDDEN];
__device__ float g_qkv[(size_t)M_ROWS * 3 * HIDDEN];
__device__ float g_ctx[(size_t)M_ROWS * HIDDEN];
__device__ float g_y  [(size_t)M_ROWS * HIDDEN];
__device__ float g_ff [(size_t)M_ROWS * FF_DIM];

// ---------------- tf32 helpers ----------------
__device__ __forceinline__ float tf32r(float x) {
    uint32_t u;
    asm("cvt.rna.tf32.f32 %0, %1;" : "=r"(u) : "f"(x));
    return __uint_as_float(u);
}
// hi/lo split: x ~= hi + lo, both exactly representable in tf32
__device__ __forceinline__ void split4(float4 v, float4& hi, float4& lo) {
    hi.x = tf32r(v.x); lo.x = tf32r(v.x - hi.x);
    hi.y = tf32r(v.y); lo.y = tf32r(v.y - hi.y);
    hi.z = tf32r(v.z); lo.z = tf32r(v.z - hi.z);
    hi.w = tf32r(v.w); lo.w = tf32r(v.w - hi.w);
}
// D = A(16x8,row) * B(8x8,col) + D, tf32 inputs, f32 accum
__device__ __forceinline__ void mma_tf32(float* c, const float* a, const float* b) {
    asm volatile(
        "mma.sync.aligned.m16n8k8.row.col.f32.tf32.tf32.f32 "
        "{%0,%1,%2,%3}, {%4,%5,%6,%7}, {%8,%9}, {%0,%1,%2,%3};\n"
        : "+f"(c[0]), "+f"(c[1]), "+f"(c[2]), "+f"(c[3])
        : "r"(__float_as_uint(a[0])), "r"(__float_as_uint(a[1])),
          "r"(__float_as_uint(a[2])), "r"(__float_as_uint(a[3])),
          "r"(__float_as_uint(b[0])), "r"(__float_as_uint(b[1])));
}
// 3xTF32: c += Ahi*Bhi + Ahi*Blo + Alo*Bhi
__device__ __forceinline__ void mma3(float* c, const float* ah, const float* al,
                                     const float* bh, const float* bl) {
    mma_tf32(c, ah, bl);
    mma_tf32(c, al, bh);
    mma_tf32(c, ah, bh);
}

// =================================================================
// Tensor-core GEMM (3xTF32): C[M,N] = A[M,K] @ W[K,N] + bias
// EPI: 0 = bias, 1 = bias+relu, 2 = bias then *32 + posenc
// BM=BN=128, BK=16, 256 threads (8 warps, 2x4), warp tile 64x32.
// =================================================================
template<int EPI>
__global__ void __launch_bounds__(256)
gemm_tc(const float* __restrict__ A, const float* __restrict__ W,
        const float* __restrict__ bias, float* __restrict__ C,
        int M, int N, int K)
{
    __shared__ __align__(16) float Ash[128][20];  // stride 20 -> conflict-free frag loads
    __shared__ __align__(16) float Asl[128][20];
    __shared__ __align__(16) float Bsh[16][132];  // stride 132 -> conflict-free frag loads
    __shared__ __align__(16) float Bsl[16][132];

    const int tid = threadIdx.x;
    const int cb = blockIdx.x * 128;
    const int rb = blockIdx.y * 128;

    const int arow = tid >> 2;          // 0..63
    const int acol = (tid & 3) * 4;     // 0,4,8,12
    const int brow = tid >> 5;          // 0..7
    const int bcol = (tid & 31) * 4;    // 0..124

    const float* Ap0 = A + (size_t)(rb + arow) * K + acol;
    const float* Ap1 = Ap0 + (size_t)64 * K;
    const float* Wp0 = W + (size_t)brow * N + cb + bcol;
    const float* Wp1 = Wp0 + (size_t)8 * N;

    const int wid = tid >> 5, lane = tid & 31;
    const int grp = lane >> 2, t4 = lane & 3;
    const int m0 = (wid >> 2) * 64;     // 0 or 64
    const int n0 = (wid & 3) * 32;      // 0,32,64,96

    float acc[4][4][4];
#pragma unroll
    for (int mt = 0; mt < 4; mt++)
#pragma unroll
        for (int nt = 0; nt < 4; nt++)
#pragma unroll
            for (int j = 0; j < 4; j++) acc[mt][nt][j] = 0.f;

    float4 ra0 = *(const float4*)(Ap0);
    float4 ra1 = *(const float4*)(Ap1);
    float4 rb0 = *(const float4*)(Wp0);
    float4 rb1 = *(const float4*)(Wp1);

    for (int k0 = 0; k0 < K; k0 += 16) {
        float4 h, l;
        split4(ra0, h, l); *(float4*)&Ash[arow][acol]      = h; *(float4*)&Asl[arow][acol]      = l;
        split4(ra1, h, l); *(float4*)&Ash[arow + 64][acol] = h; *(float4*)&Asl[arow + 64][acol] = l;
        split4(rb0, h, l); *(float4*)&Bsh[brow][bcol]      = h; *(float4*)&Bsl[brow][bcol]      = l;
        split4(rb1, h, l); *(float4*)&Bsh[brow + 8][bcol]  = h; *(float4*)&Bsl[brow + 8][bcol]  = l;
        __syncthreads();

        if (k0 + 16 < K) {   // prefetch next tile while mma runs
            ra0 = *(const float4*)(Ap0 + k0 + 16);
            ra1 = *(const float4*)(Ap1 + k0 + 16);
            rb0 = *(const float4*)(Wp0 + (size_t)(k0 + 16) * N);
            rb1 = *(const float4*)(Wp1 + (size_t)(k0 + 16) * N);
        }

#pragma unroll
        for (int k8 = 0; k8 < 16; k8 += 8) {
            float ah[4][4], al[4][4], bh[4][2], bl[4][2];
#pragma unroll
            for (int mt = 0; mt < 4; mt++) {
                int mr = m0 + mt * 16 + grp;
                ah[mt][0] = Ash[mr][k8 + t4];
                ah[mt][1] = Ash[mr + 8][k8 + t4];
                ah[mt][2] = Ash[mr][k8 + t4 + 4];
                ah[mt][3] = Ash[mr + 8][k8 + t4 + 4];
                al[mt][0] = Asl[mr][k8 + t4];
                al[mt][1] = Asl[mr + 8][k8 + t4];
                al[mt][2] = Asl[mr][k8 + t4 + 4];
                al[mt][3] = Asl[mr + 8][k8 + t4 + 4];
            }
#pragma unroll
            for (int nt = 0; nt < 4; nt++) {
                int nc = n0 + nt * 8 + grp;
                bh[nt][0] = Bsh[k8 + t4][nc];
                bh[nt][1] = Bsh[k8 + t4 + 4][nc];
                bl[nt][0] = Bsl[k8 + t4][nc];
                bl[nt][1] = Bsl[k8 + t4 + 4][nc];
            }
#pragma unroll
            for (int mt = 0; mt < 4; mt++)
#pragma unroll
                for (int nt = 0; nt < 4; nt++)
                    mma3(acc[mt][nt], ah[mt], al[mt], bh[nt], bl[nt]);
        }
        __syncthreads();
    }

    // ---- epilogue ----
#pragma unroll
    for (int mt = 0; mt < 4; mt++) {
#pragma unroll
        for (int nt = 0; nt < 4; nt++) {
            int col = cb + n0 + nt * 8 + 2 * t4;
            float b0 = bias[col], b1 = bias[col + 1];
#pragma unroll
            for (int half = 0; half < 2; half++) {
                int row = rb + m0 + mt * 16 + grp + half * 8;
                float c0 = acc[mt][nt][half * 2 + 0] + b0;
                float c1 = acc[mt][nt][half * 2 + 1] + b1;
                if (EPI == 1) { c0 = fmaxf(c0, 0.f); c1 = fmaxf(c1, 0.f); }
                if (EPI == 2) {
                    int srow = row & (SS - 1);
                    float f0 = expf(-9.210340371976184f * (float)(col & ~1) * (1.0f / 1024.0f));
                    float f1 = expf(-9.210340371976184f * (float)((col + 1) & ~1) * (1.0f / 1024.0f));
                    float a0 = (float)srow * f0, a1 = (float)srow * f1;
                    float p0 = (col & 1) ? cosf(a0) : sinf(a0);
                    float p1 = ((col + 1) & 1) ? cosf(a1) : sinf(a1);
                    c0 = c0 * 32.0f + p0;
                    c1 = c1 * 32.0f + p1;
                }
                float2 o = {c0, c1};
                *(float2*)(C + (size_t)row * N + col) = o;
            }
        }
    }
}

// =================================================================
// Flash attention, 3xTF32 tensor cores.
// Block = (b, h, 128 q-rows), 256 threads = 8 warps, warp owns 16 q rows.
// Key/value tiles of 64. qkv layout [B, S, 3, HEADS, DH].
// =================================================================
#define ASTR 68
#define ATTN_SMEM ((2 * 128 * ASTR + 2 * 64 * ASTR + 2 * 64 * ASTR + 2 * 128 * ASTR) * sizeof(float))  // 208896

__global__ void __launch_bounds__(256)
attn_tc(const float* __restrict__ qkv, float* __restrict__ ctx)
{
    extern __shared__ float sm[];
    float* Qh = sm;                  // [128][68]
    float* Ql = Qh + 128 * ASTR;
    float* Kh = Ql + 128 * ASTR;     // [64][68]
    float* Kl = Kh + 64 * ASTR;
    float* Vh = Kl + 64 * ASTR;      // [64][68]
    float* Vl = Vh + 64 * ASTR;
    float* Ph = Vl + 64 * ASTR;      // [128][68]
    float* Pl = Ph + 128 * ASTR;

    const int tid = threadIdx.x;
    const int q0 = blockIdx.x * 128;
    const int h  = blockIdx.y;
    const int b  = blockIdx.z;

    const int wid = tid >> 5, lane = tid & 31;
    const int grp = lane >> 2, t4 = lane & 3;
    const int mw = wid * 16;                 // warp's q-row base (local)

    // ---- load Q tile (128 x 64), hi/lo split ----
    {
        const float* qbase = qkv + (size_t)(b * SS + q0) * 3 * HIDDEN + h * DH;
#pragma unroll
        for (int u = 0; u < 8; u++) {
            int idx = tid + u * 256;
            int r = idx >> 4, c = (idx & 15) * 4;
            float4 v = *(const float4*)(qbase + (size_t)r * 3 * HIDDEN + c);
            float4 hi, lo;
            split4(v, hi, lo);
            *(float4*)&Qh[r * ASTR + c] = hi;
            *(float4*)&Ql[r * ASTR + c] = lo;
        }
    }

    float out[8][4];
    float mi0 = -1e30f, mi1 = -1e30f, li0 = 0.f, li1 = 0.f;
#pragma unroll
    for (int nt = 0; nt < 8; nt++)
#pragma unroll
        for (int j = 0; j < 4; j++) out[nt][j] = 0.f;

    for (int kt = 0; kt < SS / 64; kt++) {
        __syncthreads();   // everyone done with prev K/V
        {
            const float* kb = qkv + ((size_t)(b * SS + kt * 64) * 3 + 1) * HIDDEN + h * DH;
            const float* vb = kb + HIDDEN;
#pragma unroll
            for (int u = 0; u < 4; u++) {
                int idx = tid + u * 256;
                int r = idx >> 4, c = (idx & 15) * 4;
                float4 kv = *(const float4*)(kb + (size_t)r * 3 * HIDDEN + c);
                float4 vv = *(const float4*)(vb + (size_t)r * 3 * HIDDEN + c);
                float4 hi, lo;
                split4(kv, hi, lo);
                *(float4*)&Kh[r * ASTR + c] = hi;
                *(float4*)&Kl[r * ASTR + c] = lo;
                split4(vv, hi, lo);
                *(float4*)&Vh[r * ASTR + c] = hi;
                *(float4*)&Vl[r * ASTR + c] = lo;
            }
        }
        __syncthreads();

        // ---- S = Q @ K^T   (M=16 q, N=64 keys, K=64 d) ----
        float sc[8][4];
#pragma unroll
        for (int nt = 0; nt < 8; nt++)
#pragma unroll
            for (int j = 0; j < 4; j++) sc[nt][j] = 0.f;

#pragma unroll
        for (int k8 = 0; k8 < 64; k8 += 8) {
            float ah[4], al[4];
            int mr = mw + grp;
            ah[0] = Qh[mr * ASTR + k8 + t4];
            ah[1] = Qh[(mr + 8) * ASTR + k8 + t4];
            ah[2] = Qh[mr * ASTR + k8 + t4 + 4];
            ah[3] = Qh[(mr + 8) * ASTR + k8 + t4 + 4];
            al[0] = Ql[mr * ASTR + k8 + t4];
            al[1] = Ql[(mr + 8) * ASTR + k8 + t4];
            al[2] = Ql[mr * ASTR + k8 + t4 + 4];
            al[3] = Ql[(mr + 8) * ASTR + k8 + t4 + 4];
#pragma unroll
            for (int nt = 0; nt < 8; nt++) {
                float bh[2], bl[2];
                int kr = nt * 8 + grp;               // key row
                bh[0] = Kh[kr * ASTR + k8 + t4];
                bh[1] = Kh[kr * ASTR + k8 + t4 + 4];
                bl[0] = Kl[kr * ASTR + k8 + t4];
                bl[1] = Kl[kr * ASTR + k8 + t4 + 4];
                mma3(sc[nt], ah, al, bh, bl);
            }
        }

        // ---- online softmax (rows grp and grp+8 of warp band) ----
        float rm0 = -1e30f, rm1 = -1e30f;
#pragma unroll
        for (int nt = 0; nt < 8; nt++) {
#pragma unroll
            for (int j = 0; j < 4; j++) sc[nt][j] *= 0.125f;
            rm0 = fmaxf(rm0, fmaxf(sc[nt][0], sc[nt][1]));
            rm1 = fmaxf(rm1, fmaxf(sc[nt][2], sc[nt][3]));
        }
#pragma unroll
        for (int off = 1; off < 4; off <<= 1) {
            rm0 = fmaxf(rm0, __shfl_xor_sync(0xffffffffu, rm0, off));
            rm1 = fmaxf(rm1, __shfl_xor_sync(0xffffffffu, rm1, off));
        }
        float mn0 = fmaxf(mi0, rm0), mn1 = fmaxf(mi1, rm1);
        float rs0 = 0.f, rs1 = 0.f;
#pragma unroll
        for (int nt = 0; nt < 8; nt++) {
            sc[nt][0] = __expf(sc[nt][0] - mn0);
            sc[nt][1] = __expf(sc[nt][1] - mn0);
            sc[nt][2] = __expf(sc[nt][2] - mn1);
            sc[nt][3] = __expf(sc[nt][3] - mn1);
            rs0 += sc[nt][0] + sc[nt][1];
            rs1 += sc[nt][2] + sc[nt][3];
        }
#pragma unroll
        for (int off = 1; off < 4; off <<= 1) {
            rs0 += __shfl_xor_sync(0xffffffffu, rs0, off);
            rs1 += __shfl_xor_sync(0xffffffffu, rs1, off);
        }
        float al0 = __expf(mi0 - mn0), al1 = __expf(mi1 - mn1);
        li0 = li0 * al0 + rs0;
        li1 = li1 * al1 + rs1;
        mi0 = mn0; mi1 = mn1;

        // rescale accumulators, stage P (hi/lo) in smem for re-fragmenting
        int pr0 = (mw + grp) * ASTR, pr1 = (mw + grp + 8) * ASTR;
#pragma unroll
        for (int nt = 0; nt < 8; nt++) {
            out[nt][0] *= al0; out[nt][1] *= al0;
            out[nt][2] *= al1; out[nt][3] *= al1;
            int pc = nt * 8 + 2 * t4;
            float h0 = tf32r(sc[nt][0]), h1 = tf32r(sc[nt][1]);
            float h2 = tf32r(sc[nt][2]), h3 = tf32r(sc[nt][3]);
            float2 ph0 = {h0, h1}, ph1 = {h2, h3};
            float2 pl0 = {tf32r(sc[nt][0] - h0), tf32r(sc[nt][1] - h1)};
            float2 pl1 = {tf32r(sc[nt][2] - h2), tf32r(sc[nt][3] - h3)};
            *(float2*)&Ph[pr0 + pc] = ph0;
            *(float2*)&Ph[pr1 + pc] = ph1;
            *(float2*)&Pl[pr0 + pc] = pl0;
            *(float2*)&Pl[pr1 + pc] = pl1;
        }
        __syncwarp();   // warp reads only its own P rows

        // ---- out += P @ V   (M=16 q, N=64 d, K=64 keys) ----
#pragma unroll
        for (int k8 = 0; k8 < 64; k8 += 8) {
            float ah[4], al[4];
            int mr = mw + grp;
            ah[0] = Ph[mr * ASTR + k8 + t4];
            ah[1] = Ph[(mr + 8) * ASTR + k8 + t4];
            ah[2] = Ph[mr * ASTR + k8 + t4 + 4];
            ah[3] = Ph[(mr + 8) * ASTR + k8 + t4 + 4];
            al[0] = Pl[mr * ASTR + k8 + t4];
            al[1] = Pl[(mr + 8) * ASTR + k8 + t4];
            al[2] = Pl[mr * ASTR + k8 + t4 + 4];
            al[3] = Pl[(mr + 8) * ASTR + k8 + t4 + 4];
#pragma unroll
            for (int nt = 0; nt < 8; nt++) {
                float bh[2], bl[2];
                int nc = nt * 8 + grp;               // d column
                bh[0] = Vh[(k8 + t4) * ASTR + nc];
                bh[1] = Vh[(k8 + t4 + 4) * ASTR + nc];
                bl[0] = Vl[(k8 + t4) * ASTR + nc];
                bl[1] = Vl[(k8 + t4 + 4) * ASTR + nc];
                mma3(out[nt], ah, al, bh, bl);
            }
        }
    }

    // ---- write ctx ----
    float inv0 = 1.0f / li0, inv1 = 1.0f / li1;
    size_t row0 = (size_t)(b * SS + q0 + mw + grp) * HIDDEN + h * DH;
    size_t row1 = row0 + (size_t)8 * HIDDEN;
#pragma unroll
    for (int nt = 0; nt < 8; nt++) {
        int col = nt * 8 + 2 * t4;
        float2 o0 = {out[nt][0] * inv0, out[nt][1] * inv0};
        float2 o1 = {out[nt][2] * inv1, out[nt][3] * inv1};
        *(float2*)&ctx[row0 + col] = o0;
        *(float2*)&ctx[row1 + col] = o1;
    }
}

// =================================================================
// LayerNorm: one block per row of 1024.  out = LN(x + res) * g + b
// =================================================================
__global__ void __launch_bounds__(256)
ln_kernel(const float* __restrict__ x, const float* __restrict__ res,
          const float* __restrict__ g, const float* __restrict__ beta,
          float* __restrict__ out)
{
    const int row = blockIdx.x;
    const int t = threadIdx.x;

    float4 v = ((const float4*)(x + (size_t)row * HIDDEN))[t];
    if (res) {
        float4 r = ((const float4*)(res + (size_t)row * HIDDEN))[t];
        v.x += r.x; v.y += r.y; v.z += r.z; v.w += r.w;
    }
    float s  = v.x + v.y + v.z + v.w;
    float sq = v.x * v.x + v.y * v.y + v.z * v.z + v.w * v.w;

#pragma unroll
    for (int off = 16; off > 0; off >>= 1) {
        s  += __shfl_xor_sync(0xffffffffu, s,  off);
        sq += __shfl_xor_sync(0xffffffffu, sq, off);
    }
    __shared__ float ss[8], ssq[8];
    __shared__ float smean, srstd;
    int warp = t >> 5, lane = t & 31;
    if (lane == 0) { ss[warp] = s; ssq[warp] = sq; }
    __syncthreads();
    if (t == 0) {
        float S = 0.f, Q = 0.f;
#pragma unroll
        for (int i = 0; i < 8; i++) { S += ss[i]; Q += ssq[i]; }
        float mean = S * (1.0f / HIDDEN);
        float var  = Q * (1.0f / HIDDEN) - mean * mean;
        smean = mean;
        srstd = rsqrtf(var + 1e-5f);
    }
    __syncthreads();
    float mean = smean, rstd = srstd;

    float4 gg = ((const float4*)g)[t];
    float4 bb = ((const float4*)beta)[t];
    float4 o;
    o.x = (v.x - mean) * rstd * gg.x + bb.x;
    o.y = (v.y - mean) * rstd * gg.y + bb.y;
    o.z = (v.z - mean) * rstd * gg.z + bb.z;
    o.w = (v.w - mean) * rstd * gg.w + bb.w;
    ((float4*)(out + (size_t)row * HIDDEN))[t] = o;
}

// =================================================================
// launch
// =================================================================
extern "C" void kernel_launch(void* const* d_in, const int* in_sizes, int n_in,
                              void* d_out, int out_size)
{
    const float* x     = (const float*)d_in[0];
    const float* in_W  = (const float*)d_in[1];
    const float* in_b  = (const float*)d_in[2];
    const float* qkv_W = (const float*)d_in[3];
    const float* qkv_b = (const float*)d_in[4];
    const float* out_W = (const float*)d_in[5];
    const float* out_b = (const float*)d_in[6];
    const float* ln1_g = (const float*)d_in[7];
    const float* ln1_b = (const float*)d_in[8];
    const float* ln2_g = (const float*)d_in[9];
    const float* ln2_b = (const float*)d_in[10];
    const float* ff1_W = (const float*)d_in[11];
    const float* ff1_b = (const float*)d_in[12];
    const float* ff2_W = (const float*)d_in[13];
    const float* ff2_b = (const float*)d_in[14];
    const float* fin_g = (const float*)d_in[15];
    const float* fin_b = (const float*)d_in[16];
    const float* op_W  = (const float*)d_in[17];
    const float* op_b  = (const float*)d_in[18];
    float* out = (float*)d_out;

    float *h, *qkv, *ctx, *y, *ff;
    cudaGetSymbolAddress((void**)&h,   g_h);
    cudaGetSymbolAddress((void**)&qkv, g_qkv);
    cudaGetSymbolAddress((void**)&ctx, g_ctx);
    cudaGetSymbolAddress((void**)&y,   g_y);
    cudaGetSymbolAddress((void**)&ff,  g_ff);

    cudaFuncSetAttribute(attn_tc, cudaFuncAttributeMaxDynamicSharedMemorySize,
                         (int)ATTN_SMEM);

    const int M = M_ROWS;
    dim3 blk(256);

    // input projection + sqrt(H)*scale + positional encoding
    gemm_tc<2><<<dim3(HIDDEN / 128, M / 128), blk>>>(x, in_W, in_b, h, M, HIDDEN, IN_DIM);

    for (int l = 0; l < LAYERS; l++) {
        const float* qW  = qkv_W + (size_t)l * HIDDEN * 3 * HIDDEN;
        const float* qb  = qkv_b + (size_t)l * 3 * HIDDEN;
        const float* oW  = out_W + (size_t)l * HIDDEN * HIDDEN;
        const float* ob  = out_b + (size_t)l * HIDDEN;
        const float* f1W = ff1_W + (size_t)l * HIDDEN * FF_DIM;
        const float* f1b = ff1_b + (size_t)l * FF_DIM;
        const float* f2W = ff2_W + (size_t)l * FF_DIM * HIDDEN;
        const float* f2b = ff2_b + (size_t)l * HIDDEN;

        gemm_tc<0><<<dim3(3 * HIDDEN / 128, M / 128), blk>>>(h, qW, qb, qkv, M, 3 * HIDDEN, HIDDEN);
        attn_tc<<<dim3(SS / 128, HEADS, BB), blk, ATTN_SMEM>>>(qkv, ctx);
        gemm_tc<0><<<dim3(HIDDEN / 128, M / 128), blk>>>(ctx, oW, ob, y, M, HIDDEN, HIDDEN);
        ln_kernel<<<M, blk>>>(h, y, ln1_g + l * HIDDEN, ln1_b + l * HIDDEN, h);
        gemm_tc<1><<<dim3(FF_DIM / 128, M / 128), blk>>>(h, f1W, f1b, ff, M, FF_DIM, HIDDEN);
        gemm_tc<0><<<dim3(HIDDEN / 128, M / 128), blk>>>(ff, f2W, f2b, y, M, HIDDEN, FF_DIM);
        ln_kernel<<<M, blk>>>(h, y, ln2_g + l * HIDDEN, ln2_b + l * HIDDEN, h);
    }

    // final LN then output projection
    ln_kernel<<<M, blk>>>(h, nullptr, fin_g, fin_b, ctx);
    gemm_tc<0><<<dim3(OUT_DIM / 128, M / 128), blk>>>(ctx, op_W, op_b, out, M, OUT_DIM, HIDDEN);
}

// round 7
// speedup vs baseline: 1.4574x; 1.1608x over previous
#include <cuda_runtime.h>
#include <cuda_bf16.h>
#include <math.h>
#include <stdint.h>

// ---------------- problem constants ----------------
#define BB      4
#define SS      2048
#define HIDDEN  1024
#define HEADS   16
#define DH      64
#define LAYERS  4
#define IN_DIM  512
#define OUT_DIM 1024
#define FF_DIM  4096
#define M_ROWS  (BB * SS)          // 8192

// ---------------- scratch (no allocation allowed) ----------------
__device__ float g_h  [(size_t)M_ROWS * HIDDEN];
__device__ float g_qkv[(size_t)M_ROWS * 3 * HIDDEN];
__device__ float g_ctx[(size_t)M_ROWS * HIDDEN];
__device__ float g_y  [(size_t)M_ROWS * HIDDEN];
__device__ float g_ff [(size_t)M_ROWS * FF_DIM];

// ---------------- tf32 helpers ----------------
__device__ __forceinline__ float tf32r(float x) {
    uint32_t u;
    asm("cvt.rna.tf32.f32 %0, %1;" : "=r"(u) : "f"(x));
    return __uint_as_float(u);
}
__device__ __forceinline__ void split4(float4 v, float4& hi, float4& lo) {
    hi.x = tf32r(v.x); lo.x = tf32r(v.x - hi.x);
    hi.y = tf32r(v.y); lo.y = tf32r(v.y - hi.y);
    hi.z = tf32r(v.z); lo.z = tf32r(v.z - hi.z);
    hi.w = tf32r(v.w); lo.w = tf32r(v.w - hi.w);
}
// D = A(16x8,row) * B(8x8,col) + D, tf32 inputs, f32 accum
__device__ __forceinline__ void mma_tf32(float* c, const float* a, const float* b) {
    asm volatile(
        "mma.sync.aligned.m16n8k8.row.col.f32.tf32.tf32.f32 "
        "{%0,%1,%2,%3}, {%4,%5,%6,%7}, {%8,%9}, {%0,%1,%2,%3};\n"
        : "+f"(c[0]), "+f"(c[1]), "+f"(c[2]), "+f"(c[3])
        : "r"(__float_as_uint(a[0])), "r"(__float_as_uint(a[1])),
          "r"(__float_as_uint(a[2])), "r"(__float_as_uint(a[3])),
          "r"(__float_as_uint(b[0])), "r"(__float_as_uint(b[1])));
}
// 3xTF32: c += Ahi*Bhi + Ahi*Blo + Alo*Bhi
__device__ __forceinline__ void mma3(float* c, const float* ah, const float* al,
                                     const float* bh, const float* bl) {
    mma_tf32(c, ah, bl);
    mma_tf32(c, al, bh);
    mma_tf32(c, ah, bh);
}

// =================================================================
// Tensor-core GEMM (3xTF32): C[M,N] = A[M,K] @ W[K,N] + bias
// EPI: 0 = bias, 1 = bias+relu, 2 = bias then *32 + posenc
// BM=BN=128, BK=16, 256 threads (8 warps, 2x4), warp tile 64x32.
// Double-buffered dynamic smem, 2 CTAs/SM.
// =================================================================
#define A_SZ  (128 * 20)     // floats per A tile (stride 20: conflict-free frag loads)
#define B_SZ  (16 * 132)     // floats per B tile (stride 132: near-conflict-free)
#define STG   (2 * A_SZ + 2 * B_SZ)                 // floats per stage
#define GEMM_SMEM (2 * STG * sizeof(float))         // 74752 B

template<int EPI>
__global__ void __launch_bounds__(256, 2)
gemm_tc(const float* __restrict__ A, const float* __restrict__ W,
        const float* __restrict__ bias, float* __restrict__ C,
        int M, int N, int K)
{
    extern __shared__ __align__(16) float smp[];

    const int tid = threadIdx.x;
    const int cb = blockIdx.x * 128;
    const int rb = blockIdx.y * 128;

    const int arow = tid >> 2;          // 0..63
    const int acol = (tid & 3) * 4;     // 0,4,8,12
    const int brow = tid >> 5;          // 0..7
    const int bcol = (tid & 31) * 4;    // 0..124

    const float* Ap0 = A + (size_t)(rb + arow) * K + acol;
    const float* Ap1 = Ap0 + (size_t)64 * K;
    const float* Wp0 = W + (size_t)brow * N + cb + bcol;
    const float* Wp1 = Wp0 + (size_t)8 * N;

    const int wid = tid >> 5, lane = tid & 31;
    const int grp = lane >> 2, t4 = lane & 3;
    const int m0 = (wid >> 2) * 64;     // 0 or 64
    const int n0 = (wid & 3) * 32;      // 0,32,64,96

    float acc[4][4][4];
#pragma unroll
    for (int mt = 0; mt < 4; mt++)
#pragma unroll
        for (int nt = 0; nt < 4; nt++)
#pragma unroll
            for (int j = 0; j < 4; j++) acc[mt][nt][j] = 0.f;

    // ---- prologue: load + split + store tile 0 ----
    {
        float4 ra0 = *(const float4*)(Ap0);
        float4 ra1 = *(const float4*)(Ap1);
        float4 rb0 = *(const float4*)(Wp0);
        float4 rb1 = *(const float4*)(Wp1);
        float* Ah = smp;  float* Al = Ah + A_SZ;
        float* Bh = Al + A_SZ;  float* Bl = Bh + B_SZ;
        float4 h, l;
        split4(ra0, h, l); *(float4*)&Ah[arow * 20 + acol]        = h; *(float4*)&Al[arow * 20 + acol]        = l;
        split4(ra1, h, l); *(float4*)&Ah[(arow + 64) * 20 + acol] = h; *(float4*)&Al[(arow + 64) * 20 + acol] = l;
        split4(rb0, h, l); *(float4*)&Bh[brow * 132 + bcol]       = h; *(float4*)&Bl[brow * 132 + bcol]       = l;
        split4(rb1, h, l); *(float4*)&Bh[(brow + 8) * 132 + bcol] = h; *(float4*)&Bl[(brow + 8) * 132 + bcol] = l;
    }
    __syncthreads();

    int cur = 0;
    for (int k0 = 0; k0 < K; k0 += 16) {
        const bool more = (k0 + 16 < K);
        float4 ra0, ra1, rb0, rb1;
        if (more) {    // global prefetch overlaps the mma below
            ra0 = *(const float4*)(Ap0 + k0 + 16);
            ra1 = *(const float4*)(Ap1 + k0 + 16);
            rb0 = *(const float4*)(Wp0 + (size_t)(k0 + 16) * N);
            rb1 = *(const float4*)(Wp1 + (size_t)(k0 + 16) * N);
        }

        const float* Ah = smp + cur * STG;
        const float* Al = Ah + A_SZ;
        const float* Bh = Al + A_SZ;
        const float* Bl = Bh + B_SZ;

#pragma unroll
        for (int k8 = 0; k8 < 16; k8 += 8) {
            float ah[4][4], al[4][4], bh[4][2], bl[4][2];
#pragma unroll
            for (int mt = 0; mt < 4; mt++) {
                int mr = m0 + mt * 16 + grp;
                ah[mt][0] = Ah[mr * 20 + k8 + t4];
                ah[mt][1] = Ah[(mr + 8) * 20 + k8 + t4];
                ah[mt][2] = Ah[mr * 20 + k8 + t4 + 4];
                ah[mt][3] = Ah[(mr + 8) * 20 + k8 + t4 + 4];
                al[mt][0] = Al[mr * 20 + k8 + t4];
                al[mt][1] = Al[(mr + 8) * 20 + k8 + t4];
                al[mt][2] = Al[mr * 20 + k8 + t4 + 4];
                al[mt][3] = Al[(mr + 8) * 20 + k8 + t4 + 4];
            }
#pragma unroll
            for (int nt = 0; nt < 4; nt++) {
                int nc = n0 + nt * 8 + grp;
                bh[nt][0] = Bh[(k8 + t4) * 132 + nc];
                bh[nt][1] = Bh[(k8 + t4 + 4) * 132 + nc];
                bl[nt][0] = Bl[(k8 + t4) * 132 + nc];
                bl[nt][1] = Bl[(k8 + t4 + 4) * 132 + nc];
            }
#pragma unroll
            for (int mt = 0; mt < 4; mt++)
#pragma unroll
                for (int nt = 0; nt < 4; nt++)
                    mma3(acc[mt][nt], ah[mt], al[mt], bh[nt], bl[nt]);
        }

        if (more) {
            // write the OTHER stage (nobody reads it yet) then one sync
            float* Awh = smp + (cur ^ 1) * STG;
            float* Awl = Awh + A_SZ;
            float* Bwh = Awl + A_SZ;
            float* Bwl = Bwh + B_SZ;
            float4 h, l;
            split4(ra0, h, l); *(float4*)&Awh[arow * 20 + acol]        = h; *(float4*)&Awl[arow * 20 + acol]        = l;
            split4(ra1, h, l); *(float4*)&Awh[(arow + 64) * 20 + acol] = h; *(float4*)&Awl[(arow + 64) * 20 + acol] = l;
            split4(rb0, h, l); *(float4*)&Bwh[brow * 132 + bcol]       = h; *(float4*)&Bwl[brow * 132 + bcol]       = l;
            split4(rb1, h, l); *(float4*)&Bwh[(brow + 8) * 132 + bcol] = h; *(float4*)&Bwl[(brow + 8) * 132 + bcol] = l;
            __syncthreads();
            cur ^= 1;
        }
    }

    // ---- epilogue ----
#pragma unroll
    for (int mt = 0; mt < 4; mt++) {
#pragma unroll
        for (int nt = 0; nt < 4; nt++) {
            int col = cb + n0 + nt * 8 + 2 * t4;
            float b0 = bias[col], b1 = bias[col + 1];
#pragma unroll
            for (int half = 0; half < 2; half++) {
                int row = rb + m0 + mt * 16 + grp + half * 8;
                float c0 = acc[mt][nt][half * 2 + 0] + b0;
                float c1 = acc[mt][nt][half * 2 + 1] + b1;
                if (EPI == 1) { c0 = fmaxf(c0, 0.f); c1 = fmaxf(c1, 0.f); }
                if (EPI == 2) {
                    int srow = row & (SS - 1);
                    float f0 = expf(-9.210340371976184f * (float)(col & ~1) * (1.0f / 1024.0f));
                    float f1 = expf(-9.210340371976184f * (float)((col + 1) & ~1) * (1.0f / 1024.0f));
                    float a0 = (float)srow * f0, a1 = (float)srow * f1;
                    float p0 = (col & 1) ? cosf(a0) : sinf(a0);
                    float p1 = ((col + 1) & 1) ? cosf(a1) : sinf(a1);
                    c0 = c0 * 32.0f + p0;
                    c1 = c1 * 32.0f + p1;
                }
                float2 o = {c0, c1};
                *(float2*)(C + (size_t)row * N + col) = o;
            }
        }
    }
}

// =================================================================
// Flash attention, 3xTF32 tensor cores.
// Block = (b, h, 128 q-rows), 256 threads = 8 warps, warp owns 16 q rows.
// Key/value tiles of 64. qkv layout [B, S, 3, HEADS, DH].
// =================================================================
#define ASTR 68
#define ATTN_SMEM ((2 * 128 * ASTR + 2 * 64 * ASTR + 2 * 64 * ASTR + 2 * 128 * ASTR) * sizeof(float))  // 208896

__global__ void __launch_bounds__(256)
attn_tc(const float* __restrict__ qkv, float* __restrict__ ctx)
{
    extern __shared__ float sm[];
    float* Qh = sm;                  // [128][68]
    float* Ql = Qh + 128 * ASTR;
    float* Kh = Ql + 128 * ASTR;     // [64][68]
    float* Kl = Kh + 64 * ASTR;
    float* Vh = Kl + 64 * ASTR;      // [64][68]
    float* Vl = Vh + 64 * ASTR;
    float* Ph = Vl + 64 * ASTR;      // [128][68]
    float* Pl = Ph + 128 * ASTR;

    const int tid = threadIdx.x;
    const int q0 = blockIdx.x * 128;
    const int h  = blockIdx.y;
    const int b  = blockIdx.z;

    const int wid = tid >> 5, lane = tid & 31;
    const int grp = lane >> 2, t4 = lane & 3;
    const int mw = wid * 16;                 // warp's q-row base (local)

    // ---- load Q tile (128 x 64), hi/lo split ----
    {
        const float* qbase = qkv + (size_t)(b * SS + q0) * 3 * HIDDEN + h * DH;
#pragma unroll
        for (int u = 0; u < 8; u++) {
            int idx = tid + u * 256;
            int r = idx >> 4, c = (idx & 15) * 4;
            float4 v = *(const float4*)(qbase + (size_t)r * 3 * HIDDEN + c);
            float4 hi, lo;
            split4(v, hi, lo);
            *(float4*)&Qh[r * ASTR + c] = hi;
            *(float4*)&Ql[r * ASTR + c] = lo;
        }
    }

    float out[8][4];
    float mi0 = -1e30f, mi1 = -1e30f, li0 = 0.f, li1 = 0.f;
#pragma unroll
    for (int nt = 0; nt < 8; nt++)
#pragma unroll
        for (int j = 0; j < 4; j++) out[nt][j] = 0.f;

    for (int kt = 0; kt < SS / 64; kt++) {
        __syncthreads();   // everyone done with prev K/V
        {
            const float* kb = qkv + ((size_t)(b * SS + kt * 64) * 3 + 1) * HIDDEN + h * DH;
            const float* vb = kb + HIDDEN;
#pragma unroll
            for (int u = 0; u < 4; u++) {
                int idx = tid + u * 256;
                int r = idx >> 4, c = (idx & 15) * 4;
                float4 kv = *(const float4*)(kb + (size_t)r * 3 * HIDDEN + c);
                float4 vv = *(const float4*)(vb + (size_t)r * 3 * HIDDEN + c);
                float4 hi, lo;
                split4(kv, hi, lo);
                *(float4*)&Kh[r * ASTR + c] = hi;
                *(float4*)&Kl[r * ASTR + c] = lo;
                split4(vv, hi, lo);
                *(float4*)&Vh[r * ASTR + c] = hi;
                *(float4*)&Vl[r * ASTR + c] = lo;
            }
        }
        __syncthreads();

        // ---- S = Q @ K^T   (M=16 q, N=64 keys, K=64 d) ----
        float sc[8][4];
#pragma unroll
        for (int nt = 0; nt < 8; nt++)
#pragma unroll
            for (int j = 0; j < 4; j++) sc[nt][j] = 0.f;

#pragma unroll
        for (int k8 = 0; k8 < 64; k8 += 8) {
            float ah[4], al[4];
            int mr = mw + grp;
            ah[0] = Qh[mr * ASTR + k8 + t4];
            ah[1] = Qh[(mr + 8) * ASTR + k8 + t4];
            ah[2] = Qh[mr * ASTR + k8 + t4 + 4];
            ah[3] = Qh[(mr + 8) * ASTR + k8 + t4 + 4];
            al[0] = Ql[mr * ASTR + k8 + t4];
            al[1] = Ql[(mr + 8) * ASTR + k8 + t4];
            al[2] = Ql[mr * ASTR + k8 + t4 + 4];
            al[3] = Ql[(mr + 8) * ASTR + k8 + t4 + 4];
#pragma unroll
            for (int nt = 0; nt < 8; nt++) {
                float bh[2], bl[2];
                int kr = nt * 8 + grp;               // key row
                bh[0] = Kh[kr * ASTR + k8 + t4];
                bh[1] = Kh[kr * ASTR + k8 + t4 + 4];
                bl[0] = Kl[kr * ASTR + k8 + t4];
                bl[1] = Kl[kr * ASTR + k8 + t4 + 4];
                mma3(sc[nt], ah, al, bh, bl);
            }
        }

        // ---- online softmax (rows grp and grp+8 of warp band) ----
        float rm0 = -1e30f, rm1 = -1e30f;
#pragma unroll
        for (int nt = 0; nt < 8; nt++) {
#pragma unroll
            for (int j = 0; j < 4; j++) sc[nt][j] *= 0.125f;
            rm0 = fmaxf(rm0, fmaxf(sc[nt][0], sc[nt][1]));
            rm1 = fmaxf(rm1, fmaxf(sc[nt][2], sc[nt][3]));
        }
#pragma unroll
        for (int off = 1; off < 4; off <<= 1) {
            rm0 = fmaxf(rm0, __shfl_xor_sync(0xffffffffu, rm0, off));
            rm1 = fmaxf(rm1, __shfl_xor_sync(0xffffffffu, rm1, off));
        }
        float mn0 = fmaxf(mi0, rm0), mn1 = fmaxf(mi1, rm1);
        float rs0 = 0.f, rs1 = 0.f;
#pragma unroll
        for (int nt = 0; nt < 8; nt++) {
            sc[nt][0] = __expf(sc[nt][0] - mn0);
            sc[nt][1] = __expf(sc[nt][1] - mn0);
            sc[nt][2] = __expf(sc[nt][2] - mn1);
            sc[nt][3] = __expf(sc[nt][3] - mn1);
            rs0 += sc[nt][0] + sc[nt][1];
            rs1 += sc[nt][2] + sc[nt][3];
        }
#pragma unroll
        for (int off = 1; off < 4; off <<= 1) {
            rs0 += __shfl_xor_sync(0xffffffffu, rs0, off);
            rs1 += __shfl_xor_sync(0xffffffffu, rs1, off);
        }
        float al0 = __expf(mi0 - mn0), al1 = __expf(mi1 - mn1);
        li0 = li0 * al0 + rs0;
        li1 = li1 * al1 + rs1;
        mi0 = mn0; mi1 = mn1;

        // rescale accumulators, stage P (hi/lo) in smem for re-fragmenting
        int pr0 = (mw + grp) * ASTR, pr1 = (mw + grp + 8) * ASTR;
#pragma unroll
        for (int nt = 0; nt < 8; nt++) {
            out[nt][0] *= al0; out[nt][1] *= al0;
            out[nt][2] *= al1; out[nt][3] *= al1;
            int pc = nt * 8 + 2 * t4;
            float h0 = tf32r(sc[nt][0]), h1 = tf32r(sc[nt][1]);
            float h2 = tf32r(sc[nt][2]), h3 = tf32r(sc[nt][3]);
            float2 ph0 = {h0, h1}, ph1 = {h2, h3};
            float2 pl0 = {tf32r(sc[nt][0] - h0), tf32r(sc[nt][1] - h1)};
            float2 pl1 = {tf32r(sc[nt][2] - h2), tf32r(sc[nt][3] - h3)};
            *(float2*)&Ph[pr0 + pc] = ph0;
            *(float2*)&Ph[pr1 + pc] = ph1;
            *(float2*)&Pl[pr0 + pc] = pl0;
            *(float2*)&Pl[pr1 + pc] = pl1;
        }
        __syncwarp();   // warp reads only its own P rows

        // ---- out += P @ V   (M=16 q, N=64 d, K=64 keys) ----
#pragma unroll
        for (int k8 = 0; k8 < 64; k8 += 8) {
            float ah[4], al[4];
            int mr = mw + grp;
            ah[0] = Ph[mr * ASTR + k8 + t4];
            ah[1] = Ph[(mr + 8) * ASTR + k8 + t4];
            ah[2] = Ph[mr * ASTR + k8 + t4 + 4];
            ah[3] = Ph[(mr + 8) * ASTR + k8 + t4 + 4];
            al[0] = Pl[mr * ASTR + k8 + t4];
            al[1] = Pl[(mr + 8) * ASTR + k8 + t4];
            al[2] = Pl[mr * ASTR + k8 + t4 + 4];
            al[3] = Pl[(mr + 8) * ASTR + k8 + t4 + 4];
#pragma unroll
            for (int nt = 0; nt < 8; nt++) {
                float bh[2], bl[2];
                int nc = nt * 8 + grp;               // d column
                bh[0] = Vh[(k8 + t4) * ASTR + nc];
                bh[1] = Vh[(k8 + t4 + 4) * ASTR + nc];
                bl[0] = Vl[(k8 + t4) * ASTR + nc];
                bl[1] = Vl[(k8 + t4 + 4) * ASTR + nc];
                mma3(out[nt], ah, al, bh, bl);
            }
        }
    }

    // ---- write ctx ----
    float inv0 = 1.0f / li0, inv1 = 1.0f / li1;
    size_t row0 = (size_t)(b * SS + q0 + mw + grp) * HIDDEN + h * DH;
    size_t row1 = row0 + (size_t)8 * HIDDEN;
#pragma unroll
    for (int nt = 0; nt < 8; nt++) {
        int col = nt * 8 + 2 * t4;
        float2 o0 = {out[nt][0] * inv0, out[nt][1] * inv0};
        float2 o1 = {out[nt][2] * inv1, out[nt][3] * inv1};
        *(float2*)&ctx[row0 + col] = o0;
        *(float2*)&ctx[row1 + col] = o1;
    }
}

// =================================================================
// LayerNorm: one block per row of 1024.  out = LN(x + res) * g + b
// =================================================================
__global__ void __launch_bounds__(256)
ln_kernel(const float* __restrict__ x, const float* __restrict__ res,
          const float* __restrict__ g, const float* __restrict__ beta,
          float* __restrict__ out)
{
    const int row = blockIdx.x;
    const int t = threadIdx.x;

    float4 v = ((const float4*)(x + (size_t)row * HIDDEN))[t];
    if (res) {
        float4 r = ((const float4*)(res + (size_t)row * HIDDEN))[t];
        v.x += r.x; v.y += r.y; v.z += r.z; v.w += r.w;
    }
    float s  = v.x + v.y + v.z + v.w;
    float sq = v.x * v.x + v.y * v.y + v.z * v.z + v.w * v.w;

#pragma unroll
    for (int off = 16; off > 0; off >>= 1) {
        s  += __shfl_xor_sync(0xffffffffu, s,  off);
        sq += __shfl_xor_sync(0xffffffffu, sq, off);
    }
    __shared__ float ss[8], ssq[8];
    __shared__ float smean, srstd;
    int warp = t >> 5, lane = t & 31;
    if (lane == 0) { ss[warp] = s; ssq[warp] = sq; }
    __syncthreads();
    if (t == 0) {
        float S = 0.f, Q = 0.f;
#pragma unroll
        for (int i = 0; i < 8; i++) { S += ss[i]; Q += ssq[i]; }
        float mean = S * (1.0f / HIDDEN);
        float var  = Q * (1.0f / HIDDEN) - mean * mean;
        smean = mean;
        srstd = rsqrtf(var + 1e-5f);
    }
    __syncthreads();
    float mean = smean, rstd = srstd;

    float4 gg = ((const float4*)g)[t];
    float4 bb = ((const float4*)beta)[t];
    float4 o;
    o.x = (v.x - mean) * rstd * gg.x + bb.x;
    o.y = (v.y - mean) * rstd * gg.y + bb.y;
    o.z = (v.z - mean) * rstd * gg.z + bb.z;
    o.w = (v.w - mean) * rstd * gg.w + bb.w;
    ((float4*)(out + (size_t)row * HIDDEN))[t] = o;
}

// =================================================================
// launch
// =================================================================
extern "C" void kernel_launch(void* const* d_in, const int* in_sizes, int n_in,
                              void* d_out, int out_size)
{
    const float* x     = (const float*)d_in[0];
    const float* in_W  = (const float*)d_in[1];
    const float* in_b  = (const float*)d_in[2];
    const float* qkv_W = (const float*)d_in[3];
    const float* qkv_b = (const float*)d_in[4];
    const float* out_W = (const float*)d_in[5];
    const float* out_b = (const float*)d_in[6];
    const float* ln1_g = (const float*)d_in[7];
    const float* ln1_b = (const float*)d_in[8];
    const float* ln2_g = (const float*)d_in[9];
    const float* ln2_b = (const float*)d_in[10];
    const float* ff1_W = (const float*)d_in[11];
    const float* ff1_b = (const float*)d_in[12];
    const float* ff2_W = (const float*)d_in[13];
    const float* ff2_b = (const float*)d_in[14];
    const float* fin_g = (const float*)d_in[15];
    const float* fin_b = (const float*)d_in[16];
    const float* op_W  = (const float*)d_in[17];
    const float* op_b  = (const float*)d_in[18];
    float* out = (float*)d_out;

    float *h, *qkv, *ctx, *y, *ff;
    cudaGetSymbolAddress((void**)&h,   g_h);
    cudaGetSymbolAddress((void**)&qkv, g_qkv);
    cudaGetSymbolAddress((void**)&ctx, g_ctx);
    cudaGetSymbolAddress((void**)&y,   g_y);
    cudaGetSymbolAddress((void**)&ff,  g_ff);

    cudaFuncSetAttribute(attn_tc, cudaFuncAttributeMaxDynamicSharedMemorySize,
                         (int)ATTN_SMEM);
    cudaFuncSetAttribute(gemm_tc<0>, cudaFuncAttributeMaxDynamicSharedMemorySize,
                         (int)GEMM_SMEM);
    cudaFuncSetAttribute(gemm_tc<1>, cudaFuncAttributeMaxDynamicSharedMemorySize,
                         (int)GEMM_SMEM);
    cudaFuncSetAttribute(gemm_tc<2>, cudaFuncAttributeMaxDynamicSharedMemorySize,
                         (int)GEMM_SMEM);

    const int M = M_ROWS;
    dim3 blk(256);

    // input projection + sqrt(H)*scale + positional encoding
    gemm_tc<2><<<dim3(HIDDEN / 128, M / 128), blk, GEMM_SMEM>>>(x, in_W, in_b, h, M, HIDDEN, IN_DIM);

    for (int l = 0; l < LAYERS; l++) {
        const float* qW  = qkv_W + (size_t)l * HIDDEN * 3 * HIDDEN;
        const float* qb  = qkv_b + (size_t)l * 3 * HIDDEN;
        const float* oW  = out_W + (size_t)l * HIDDEN * HIDDEN;
        const float* ob  = out_b + (size_t)l * HIDDEN;
        const float* f1W = ff1_W + (size_t)l * HIDDEN * FF_DIM;
        const float* f1b = ff1_b + (size_t)l * FF_DIM;
        const float* f2W = ff2_W + (size_t)l * FF_DIM * HIDDEN;
        const float* f2b = ff2_b + (size_t)l * HIDDEN;

        gemm_tc<0><<<dim3(3 * HIDDEN / 128, M / 128), blk, GEMM_SMEM>>>(h, qW, qb, qkv, M, 3 * HIDDEN, HIDDEN);
        attn_tc<<<dim3(SS / 128, HEADS, BB), blk, ATTN_SMEM>>>(qkv, ctx);
        gemm_tc<0><<<dim3(HIDDEN / 128, M / 128), blk, GEMM_SMEM>>>(ctx, oW, ob, y, M, HIDDEN, HIDDEN);
        ln_kernel<<<M, blk>>>(h, y, ln1_g + l * HIDDEN, ln1_b + l * HIDDEN, h);
        gemm_tc<1><<<dim3(FF_DIM / 128, M / 128), blk, GEMM_SMEM>>>(h, f1W, f1b, ff, M, FF_DIM, HIDDEN);
        gemm_tc<0><<<dim3(HIDDEN / 128, M / 128), blk, GEMM_SMEM>>>(ff, f2W, f2b, y, M, HIDDEN, FF_DIM);
        ln_kernel<<<M, blk>>>(h, y, ln2_g + l * HIDDEN, ln2_b + l * HIDDEN, h);
    }

    // final LN then output projection
    ln_kernel<<<M, blk>>>(h, nullptr, fin_g, fin_b, ctx);
    gemm_tc<0><<<dim3(OUT_DIM / 128, M / 128), blk, GEMM_SMEM>>>(ctx, op_W, op_b, out, M, OUT_DIM, HIDDEN);
}